// round 1
// baseline (speedup 1.0000x reference)
#include <cuda_runtime.h>

#define M_NODES   8192
#define K_PAR     8
#define C_CFG     256
#define N_LAYERS  8

__device__ __forceinline__ float fast_sigmoid(float x) {
    // sigmoid(x) = 1 / (1 + exp(-x)) ; exp(-x) = exp2(-x*log2(e))
    float t = -1.4426950408889634f * x;
    float e;
    asm("ex2.approx.f32 %0, %1;" : "=f"(e) : "f"(t));
    float d = 1.0f + e;
    float r;
    asm("rcp.approx.f32 %0, %1;" : "=f"(r) : "f"(d));
    return r;
}

__global__ void root_kernel(const float* __restrict__ root_logits,
                            float* __restrict__ out) {
    int i = blockIdx.x * blockDim.x + threadIdx.x;
    if (i < M_NODES) out[i] = fast_sigmoid(root_logits[i]);
}

// One warp per node. Lane L holds configs c = 8L .. 8L+7.
// Config bit (K-1-j) corresponds to parent j (MSB-first, matching reference).
//   c bits 0..2  (within-lane index t bits) -> parents 7,6,5
//   c bits 3..7  (lane bits 0..4)           -> parents 4,3,2,1,0
__global__ void layer_kernel(const float* __restrict__ cpt,     // [M, C]
                             const int*   __restrict__ parents, // [M, K]
                             const float* __restrict__ prev,    // [M]
                             float*       __restrict__ out)     // [M]
{
    int warp = (blockIdx.x * blockDim.x + threadIdx.x) >> 5;
    int lane = threadIdx.x & 31;
    if (warp >= M_NODES) return;
    const int node = warp;

    // Lanes gather parent marginals (lane&7 picks parent j); broadcast all 8.
    int   pidx = parents[node * K_PAR + (lane & 7)];
    float pp   = prev[pidx];
    float p[8];
#pragma unroll
    for (int j = 0; j < 8; j++) p[j] = __shfl_sync(0xffffffffu, pp, j);

    // Load this lane's 8 CPT logits (contiguous, 2x float4) and sigmoid them.
    const float4* base = reinterpret_cast<const float4*>(cpt + (size_t)node * C_CFG + lane * 8);
    float4 a = base[0];
    float4 b = base[1];
    float s[8];
    s[0] = fast_sigmoid(a.x); s[1] = fast_sigmoid(a.y);
    s[2] = fast_sigmoid(a.z); s[3] = fast_sigmoid(a.w);
    s[4] = fast_sigmoid(b.x); s[5] = fast_sigmoid(b.y);
    s[6] = fast_sigmoid(b.z); s[7] = fast_sigmoid(b.w);

    // In-lane folds: contract parents 7, 6, 5 (config bits 0,1,2).
    float r4[4];
#pragma unroll
    for (int u = 0; u < 4; u++)
        r4[u] = s[2 * u] + p[7] * (s[2 * u + 1] - s[2 * u]);
    float r2[2];
#pragma unroll
    for (int v = 0; v < 2; v++)
        r2[v] = r4[2 * v] + p[6] * (r4[2 * v + 1] - r4[2 * v]);
    float r = r2[0] + p[5] * (r2[1] - r2[0]);

    // Cross-lane butterfly folds: lane bit b -> config bit b+3 -> parent 4-b.
#pragma unroll
    for (int bbit = 0; bbit < 5; bbit++) {
        int   msk = 1 << bbit;
        float o   = __shfl_xor_sync(0xffffffffu, r, msk);
        float v0  = (lane & msk) ? o : r;  // value with this config bit = 0
        float v1  = (lane & msk) ? r : o;  // value with this config bit = 1
        r = v0 + p[4 - bbit] * (v1 - v0);
    }

    if (lane == 0) out[node] = r;
}

extern "C" void kernel_launch(void* const* d_in, const int* in_sizes, int n_in,
                              void* d_out, int out_size) {
    const float* root    = (const float*)d_in[0];  // [M]
    const float* cpt     = (const float*)d_in[1];  // [N_LAYERS, M, C]
    const int*   parents = (const int*)  d_in[2];  // [N_LAYERS, M, K]
    float*       out     = (float*)d_out;          // [(N_LAYERS+1) * M]

    root_kernel<<<(M_NODES + 255) / 256, 256>>>(root, out);

    // 8 warps/block -> 1024 blocks per layer; stream order gives the layer
    // dependency (layer l reads out[l*M .. ], writes out[(l+1)*M .. ]).
    for (int l = 0; l < N_LAYERS; l++) {
        layer_kernel<<<M_NODES / 8, 256>>>(
            cpt     + (size_t)l * M_NODES * C_CFG,
            parents + (size_t)l * M_NODES * K_PAR,
            out     + (size_t)l * M_NODES,
            out     + (size_t)(l + 1) * M_NODES);
    }
}

// round 2
// speedup vs baseline: 1.0082x; 1.0082x over previous
#include <cuda_runtime.h>

#define M_NODES   8192
#define K_PAR     8
#define C_CFG     256
#define N_LAYERS  8

__device__ __forceinline__ float fast_sigmoid(float x) {
    // sigmoid(x) = 1 / (1 + exp(-x)) ; exp(-x) = exp2(-x*log2(e))
    float t = -1.4426950408889634f * x;
    float e;
    asm("ex2.approx.f32 %0, %1;" : "=f"(e) : "f"(t));
    float d = 1.0f + e;
    float r;
    asm("rcp.approx.f32 %0, %1;" : "=f"(r) : "f"(d));
    return r;
}

__global__ void root_kernel(const float* __restrict__ root_logits,
                            float* __restrict__ out) {
    int i = blockIdx.x * blockDim.x + threadIdx.x;
    if (i < M_NODES) out[i] = fast_sigmoid(root_logits[i]);
}

// 8 lanes per node, 4 nodes per warp.
// Lane (group-lane gl = lane&7) iteration i holds configs c = (i*8+gl)*4 + t.
// Config bit b corresponds to parent (7-b)  [MSB-first reference convention]:
//   bits 0-1 (t)        -> parents 7,6  : folded per float4 (in registers)
//   bits 2-4 (gl)       -> parents 5,4,3: folded via 3 shfl_xor within group
//   bits 5-7 (iter i)   -> parents 2,1,0: folded in registers across iters
__global__ void layer_kernel(const float* __restrict__ cpt,     // [M, C]
                             const int*   __restrict__ parents, // [M, K]
                             const float* __restrict__ prev,    // [M]
                             float*       __restrict__ out)     // [M]
{
    const int warp = (blockIdx.x * blockDim.x + threadIdx.x) >> 5;
    const int lane = threadIdx.x & 31;
    const int gl   = lane & 7;
    const int node = warp * 4 + (lane >> 3);

    // --- Parent gather: lane l loads parents[warp*32 + l] (coalesced),
    //     gathers prev, then group-local broadcasts.
    int   pidx = parents[warp * 32 + lane];   // node (warp*4 + l>>3), parent (l&7)
    float pp   = prev[pidx];
    float p[8];
    const int pbase = lane & 24;
#pragma unroll
    for (int j = 0; j < 8; j++)
        p[j] = __shfl_sync(0xffffffffu, pp, pbase | j);

    // --- CPT streaming + fold (parents 7,6 per float4; parents 2,1,0 across iters)
    const float4* base = reinterpret_cast<const float4*>(
        cpt + (size_t)node * C_CFG + gl * 4);
    float r_i[8];
#pragma unroll
    for (int i = 0; i < 8; i++) {
        float4 v = base[i * 8];  // config floats c = i*32 + gl*4 .. +3
        float s0 = fast_sigmoid(v.x);
        float s1 = fast_sigmoid(v.y);
        float s2 = fast_sigmoid(v.z);
        float s3 = fast_sigmoid(v.w);
        float t0 = fmaf(p[7], s1 - s0, s0);
        float t1 = fmaf(p[7], s3 - s2, s2);
        r_i[i]   = fmaf(p[6], t1 - t0, t0);
    }
    // iter bit0 -> parent 2
    float q0 = fmaf(p[2], r_i[1] - r_i[0], r_i[0]);
    float q1 = fmaf(p[2], r_i[3] - r_i[2], r_i[2]);
    float q2 = fmaf(p[2], r_i[5] - r_i[4], r_i[4]);
    float q3 = fmaf(p[2], r_i[7] - r_i[6], r_i[6]);
    // iter bit1 -> parent 1
    float h0 = fmaf(p[1], q1 - q0, q0);
    float h1 = fmaf(p[1], q3 - q2, q2);
    // iter bit2 -> parent 0
    float r = fmaf(p[0], h1 - h0, h0);

    // --- Cross-lane folds within the 8-lane group: gl bit b -> parent 5-b.
#pragma unroll
    for (int b = 0; b < 3; b++) {
        int   msk = 1 << b;
        float o   = __shfl_xor_sync(0xffffffffu, r, msk);
        float v0  = (lane & msk) ? o : r;   // config bit = 0 value
        float v1  = (lane & msk) ? r : o;   // config bit = 1 value
        r = fmaf(p[5 - b], v1 - v0, v0);
    }

    if (gl == 0) out[node] = r;
}

extern "C" void kernel_launch(void* const* d_in, const int* in_sizes, int n_in,
                              void* d_out, int out_size) {
    const float* root    = (const float*)d_in[0];  // [M]
    const float* cpt     = (const float*)d_in[1];  // [N_LAYERS, M, C]
    const int*   parents = (const int*)  d_in[2];  // [N_LAYERS, M, K]
    float*       out     = (float*)d_out;          // [(N_LAYERS+1) * M]

    root_kernel<<<(M_NODES + 255) / 256, 256>>>(root, out);

    // 32 nodes per 256-thread block -> 256 blocks per layer.
    for (int l = 0; l < N_LAYERS; l++) {
        layer_kernel<<<M_NODES / 32, 256>>>(
            cpt     + (size_t)l * M_NODES * C_CFG,
            parents + (size_t)l * M_NODES * K_PAR,
            out     + (size_t)l * M_NODES,
            out     + (size_t)(l + 1) * M_NODES);
    }
}